// round 1
// baseline (speedup 1.0000x reference)
#include <cuda_runtime.h>

#define DIM 32
#define NODES_MAX 100000
#define EDGES_MAX 3200000
#define SCAN_BLK 1024
#define NB_MAX 128   // ceil(100000/1024)=98

// ---------------- scratch (device globals; no allocation allowed) ------------
__device__ float g_p0[NODES_MAX * DIM];
__device__ float g_p1[NODES_MAX * DIM];
__device__ int   g_deg[NODES_MAX];
__device__ int   g_row[NODES_MAX + 1];
__device__ int   g_wcur[NODES_MAX];
__device__ int   g_ssrc[EDGES_MAX];
__device__ int   g_bsum[NB_MAX];
__device__ int   g_bsum_ex[NB_MAX];
__device__ float g_pool[DIM];

// ---------------- small init ------------------------------------------------
__global__ void k_zero(int n_nodes) {
    int stride = gridDim.x * blockDim.x;
    for (int i = blockIdx.x * blockDim.x + threadIdx.x; i < n_nodes; i += stride)
        g_deg[i] = 0;
    if (blockIdx.x == 0 && threadIdx.x < DIM) g_pool[threadIdx.x] = 0.0f;
}

// ---------------- CSR build -------------------------------------------------
__global__ void k_hist(const int* __restrict__ dst, int n_edges) {
    int stride = gridDim.x * blockDim.x;
    for (int i = blockIdx.x * blockDim.x + threadIdx.x; i < n_edges; i += stride)
        atomicAdd(&g_deg[dst[i]], 1);
}

__global__ void k_scan1(int n_nodes) {
    __shared__ int s[SCAN_BLK];
    int tid = threadIdx.x;
    int i = blockIdx.x * SCAN_BLK + tid;
    int v = (i < n_nodes) ? g_deg[i] : 0;
    s[tid] = v;
    __syncthreads();
    for (int off = 1; off < SCAN_BLK; off <<= 1) {
        int t = (tid >= off) ? s[tid - off] : 0;
        __syncthreads();
        s[tid] += t;
        __syncthreads();
    }
    if (i < n_nodes) g_row[i] = s[tid] - v;  // local exclusive
    if (tid == SCAN_BLK - 1) g_bsum[blockIdx.x] = s[tid];
}

__global__ void k_scan2(int nb) {
    __shared__ int s[NB_MAX];
    int tid = threadIdx.x;
    int v = (tid < nb) ? g_bsum[tid] : 0;
    s[tid] = v;
    __syncthreads();
    for (int off = 1; off < NB_MAX; off <<= 1) {
        int t = (tid >= off) ? s[tid - off] : 0;
        __syncthreads();
        s[tid] += t;
        __syncthreads();
    }
    g_bsum_ex[tid] = s[tid] - v;  // exclusive
}

__global__ void k_scan3(int n_nodes, int n_edges) {
    int stride = gridDim.x * blockDim.x;
    int gid = blockIdx.x * blockDim.x + threadIdx.x;
    for (int i = gid; i < n_nodes; i += stride) {
        int r = g_row[i] + g_bsum_ex[i / SCAN_BLK];
        g_row[i] = r;
        g_wcur[i] = r;
    }
    if (gid == 0) g_row[n_nodes] = n_edges;
}

__global__ void k_fill(const int* __restrict__ src, const int* __restrict__ dst,
                       int n_edges) {
    int stride = gridDim.x * blockDim.x;
    for (int i = blockIdx.x * blockDim.x + threadIdx.x; i < n_edges; i += stride) {
        int pos = atomicAdd(&g_wcur[dst[i]], 1);
        g_ssrc[pos] = src[i];
    }
}

// ---------------- input projection: p0 = x @ w1a -----------------------------
__global__ void k_proj(const float* __restrict__ x, const float* __restrict__ w1a,
                       int n_nodes, int in_dim) {
    __shared__ float ws[80 * DIM];
    for (int i = threadIdx.x; i < in_dim * DIM; i += blockDim.x) ws[i] = w1a[i];
    __syncthreads();
    int lane = threadIdx.x & 31;
    int warp = (blockIdx.x * blockDim.x + threadIdx.x) >> 5;
    int nwarp = (gridDim.x * blockDim.x) >> 5;
    for (int n = warp; n < n_nodes; n += nwarp) {
        const float* xr = x + (size_t)n * in_dim;
        float acc = 0.0f;
        for (int k = 0; k < in_dim; k++)
            acc = fmaf(__ldg(&xr[k]), ws[k * DIM + lane], acc);
        g_p0[n * DIM + lane] = acc;
    }
}

// ---------------- fused GIN layer --------------------------------------------
// Input:  p_in[n] = h_l[n] @ Wa_l (projection already applied)
// Output: p_out[n] = relu(relu(segsum(p_in[src]) + p_in[n] + Ba) @ Wb + Bb) @ Wa_next
// If LAST: accumulate pooled sum of u = relu(...) into g_pool instead.
template <bool LAST>
__global__ void __launch_bounds__(256)
k_layer(const float* __restrict__ p_in, float* __restrict__ p_out,
        const float* __restrict__ Wb, const float* __restrict__ Bbv,
        const float* __restrict__ Bav, const float* __restrict__ Wanext,
        int n_nodes) {
    int lane = threadIdx.x & 31;
    float wbc[DIM];
#pragma unroll
    for (int k = 0; k < DIM; k++) wbc[k] = Wb[k * DIM + lane];
    float wac[DIM];
    if (!LAST) {
#pragma unroll
        for (int k = 0; k < DIM; k++) wac[k] = Wanext[k * DIM + lane];
    }
    float bav = Bav[lane], bbv = Bbv[lane];

    int warp = (blockIdx.x * blockDim.x + threadIdx.x) >> 5;
    int nwarp = (gridDim.x * blockDim.x) >> 5;
    float pool = 0.0f;

    for (int n = warp; n < n_nodes; n += nwarp) {
        int beg = g_row[n];
        int end = g_row[n + 1];
        float a0 = 0.f, a1 = 0.f, a2 = 0.f, a3 = 0.f;
        float a4 = 0.f, a5 = 0.f, a6 = 0.f, a7 = 0.f;
        int e = beg;
        for (; e + 8 <= end; e += 8) {
            int s0 = g_ssrc[e + 0], s1 = g_ssrc[e + 1];
            int s2 = g_ssrc[e + 2], s3 = g_ssrc[e + 3];
            int s4 = g_ssrc[e + 4], s5 = g_ssrc[e + 5];
            int s6 = g_ssrc[e + 6], s7 = g_ssrc[e + 7];
            a0 += p_in[s0 * DIM + lane];
            a1 += p_in[s1 * DIM + lane];
            a2 += p_in[s2 * DIM + lane];
            a3 += p_in[s3 * DIM + lane];
            a4 += p_in[s4 * DIM + lane];
            a5 += p_in[s5 * DIM + lane];
            a6 += p_in[s6 * DIM + lane];
            a7 += p_in[s7 * DIM + lane];
        }
        for (; e < end; ++e) a0 += p_in[g_ssrc[e] * DIM + lane];

        float t = ((a0 + a1) + (a2 + a3)) + ((a4 + a5) + (a6 + a7));
        t += p_in[n * DIM + lane] + bav;
        t = fmaxf(t, 0.0f);

        float u = bbv;
#pragma unroll
        for (int k = 0; k < DIM; k++)
            u = fmaf(__shfl_sync(0xffffffffu, t, k), wbc[k], u);
        u = fmaxf(u, 0.0f);

        if (!LAST) {
            float o = 0.0f;
#pragma unroll
            for (int k = 0; k < DIM; k++)
                o = fmaf(__shfl_sync(0xffffffffu, u, k), wac[k], o);
            p_out[n * DIM + lane] = o;
        } else {
            pool += u;
        }
    }

    if (LAST) {
        __shared__ float sp[8][DIM];
        int w = threadIdx.x >> 5;
        sp[w][lane] = pool;
        __syncthreads();
        if (w == 0) {
            float s = 0.0f;
#pragma unroll
            for (int i = 0; i < 8; i++) s += sp[i][lane];
            atomicAdd(&g_pool[lane], s);
        }
    }
}

// ---------------- head: out = relu(pool @ fc_w + fc_b) @ out_w + out_b -------
__global__ void k_head(const float* __restrict__ fcw, const float* __restrict__ fcb,
                       const float* __restrict__ outw, const float* __restrict__ outb,
                       float* __restrict__ out) {
    __shared__ float g2[DIM];
    int j = threadIdx.x;
    float acc = fcb[j];
    for (int k = 0; k < DIM; k++) acc = fmaf(g_pool[k], fcw[k * DIM + j], acc);
    g2[j] = fmaxf(acc, 0.0f);
    __syncwarp();
    float o = outb[j];
    for (int k = 0; k < DIM; k++) o = fmaf(g2[k], outw[k * DIM + j], o);
    out[j] = o;
}

// ---------------- launch ------------------------------------------------------
extern "C" void kernel_launch(void* const* d_in, const int* in_sizes, int n_in,
                              void* d_out, int out_size) {
    const float* x    = (const float*)d_in[0];
    const int*   ei   = (const int*)d_in[1];
    const float* w1a  = (const float*)d_in[2];
    const float* b1a  = (const float*)d_in[3];
    const float* w1b  = (const float*)d_in[4];
    const float* b1b  = (const float*)d_in[5];
    const float* wa   = (const float*)d_in[6];
    const float* ba   = (const float*)d_in[7];
    const float* wb   = (const float*)d_in[8];
    const float* bb   = (const float*)d_in[9];
    const float* fcw  = (const float*)d_in[10];
    const float* fcb  = (const float*)d_in[11];
    const float* outw = (const float*)d_in[12];
    const float* outb = (const float*)d_in[13];

    int in_dim  = in_sizes[2] / DIM;           // w1a is (in_dim, 32)
    int n_nodes = in_sizes[0] / in_dim;        // x is (n, in_dim)
    int n_edges = in_sizes[1] / 2;             // edge_index is (2, E)
    const int* src = ei;
    const int* dst = ei + n_edges;

    float *p0, *p1;
    cudaGetSymbolAddress((void**)&p0, g_p0);
    cudaGetSymbolAddress((void**)&p1, g_p1);

    // CSR build + zero pool
    k_zero<<<256, 256>>>(n_nodes);
    k_hist<<<2048, 256>>>(dst, n_edges);
    int nb = (n_nodes + SCAN_BLK - 1) / SCAN_BLK;
    k_scan1<<<nb, SCAN_BLK>>>(n_nodes);
    k_scan2<<<1, NB_MAX>>>(nb);
    k_scan3<<<256, 256>>>(n_nodes, n_edges);
    k_fill<<<2048, 256>>>(src, dst, n_edges);

    // projection to first-layer pre-aggregation space
    k_proj<<<1024, 256>>>(x, w1a, n_nodes, in_dim);

    // 5 fused GIN layers (double-buffered p)
    k_layer<false><<<2048, 256>>>(p0, p1, w1b, b1b, b1a, wa + 0 * DIM * DIM, n_nodes);
    k_layer<false><<<2048, 256>>>(p1, p0, wb + 0 * DIM * DIM, bb + 0 * DIM, ba + 0 * DIM,
                                  wa + 1 * DIM * DIM, n_nodes);
    k_layer<false><<<2048, 256>>>(p0, p1, wb + 1 * DIM * DIM, bb + 1 * DIM, ba + 1 * DIM,
                                  wa + 2 * DIM * DIM, n_nodes);
    k_layer<false><<<2048, 256>>>(p1, p0, wb + 2 * DIM * DIM, bb + 2 * DIM, ba + 2 * DIM,
                                  wa + 3 * DIM * DIM, n_nodes);
    k_layer<true><<<2048, 256>>>(p0, nullptr, wb + 3 * DIM * DIM, bb + 3 * DIM,
                                 ba + 3 * DIM, nullptr, n_nodes);

    // graph head
    k_head<<<1, 32>>>(fcw, fcb, outw, outb, (float*)d_out);
}

// round 2
// speedup vs baseline: 1.5393x; 1.5393x over previous
#include <cuda_runtime.h>
#include <cuda_fp16.h>

#define DIM 32
#define NODES_MAX 100000
#define EDGES_MAX 3200000
#define SCAN_BLK 1024
#define NB_MAX 128   // ceil(100000/1024)=98

// ---------------- scratch (device globals; no allocation allowed) ------------
__device__ __half g_p0[NODES_MAX * DIM];
__device__ __half g_p1[NODES_MAX * DIM];
__device__ int    g_deg[NODES_MAX];
__device__ int    g_row[NODES_MAX + 1];
__device__ int    g_wcur[NODES_MAX];
__device__ int    g_ssrc[EDGES_MAX];
__device__ int    g_bsum[NB_MAX];
__device__ int    g_bsum_ex[NB_MAX];
__device__ float  g_pool[DIM];

// ---------------- small init ------------------------------------------------
__global__ void k_zero(int n_nodes) {
    int stride = gridDim.x * blockDim.x;
    for (int i = blockIdx.x * blockDim.x + threadIdx.x; i < n_nodes; i += stride)
        g_deg[i] = 0;
    if (blockIdx.x == 0 && threadIdx.x < DIM) g_pool[threadIdx.x] = 0.0f;
}

// ---------------- CSR build -------------------------------------------------
__global__ void k_hist(const int* __restrict__ dst, int n_edges) {
    int stride = gridDim.x * blockDim.x;
    for (int i = blockIdx.x * blockDim.x + threadIdx.x; i < n_edges; i += stride)
        atomicAdd(&g_deg[__ldg(&dst[i])], 1);
}

__global__ void k_scan1(int n_nodes) {
    __shared__ int s[SCAN_BLK];
    int tid = threadIdx.x;
    int i = blockIdx.x * SCAN_BLK + tid;
    int v = (i < n_nodes) ? g_deg[i] : 0;
    s[tid] = v;
    __syncthreads();
    for (int off = 1; off < SCAN_BLK; off <<= 1) {
        int t = (tid >= off) ? s[tid - off] : 0;
        __syncthreads();
        s[tid] += t;
        __syncthreads();
    }
    if (i < n_nodes) g_row[i] = s[tid] - v;  // local exclusive
    if (tid == SCAN_BLK - 1) g_bsum[blockIdx.x] = s[tid];
}

__global__ void k_scan2(int nb) {
    __shared__ int s[NB_MAX];
    int tid = threadIdx.x;
    int v = (tid < nb) ? g_bsum[tid] : 0;
    s[tid] = v;
    __syncthreads();
    for (int off = 1; off < NB_MAX; off <<= 1) {
        int t = (tid >= off) ? s[tid - off] : 0;
        __syncthreads();
        s[tid] += t;
        __syncthreads();
    }
    g_bsum_ex[tid] = s[tid] - v;  // exclusive
}

__global__ void k_scan3(int n_nodes, int n_edges) {
    int stride = gridDim.x * blockDim.x;
    int gid = blockIdx.x * blockDim.x + threadIdx.x;
    for (int i = gid; i < n_nodes; i += stride) {
        int r = g_row[i] + g_bsum_ex[i / SCAN_BLK];
        g_row[i] = r;
        g_wcur[i] = r;
    }
    if (gid == 0) g_row[n_nodes] = n_edges;
}

__global__ void k_fill(const int* __restrict__ src, const int* __restrict__ dst,
                       int n_edges) {
    int stride = gridDim.x * blockDim.x;
    for (int i = blockIdx.x * blockDim.x + threadIdx.x; i < n_edges; i += stride) {
        int pos = atomicAdd(&g_wcur[__ldg(&dst[i])], 1);
        g_ssrc[pos] = __ldg(&src[i]);
    }
}

// ---------------- input projection: p0 = x @ w1a (half output) ---------------
__global__ void k_proj(const float* __restrict__ x, const float* __restrict__ w1a,
                       int n_nodes, int in_dim) {
    __shared__ float ws[80 * DIM];
    for (int i = threadIdx.x; i < in_dim * DIM; i += blockDim.x) ws[i] = w1a[i];
    __syncthreads();
    int lane = threadIdx.x & 31;
    int warp = (blockIdx.x * blockDim.x + threadIdx.x) >> 5;
    int nwarp = (gridDim.x * blockDim.x) >> 5;
    for (int n = warp; n < n_nodes; n += nwarp) {
        const float* xr = x + (size_t)n * in_dim;
        float acc = 0.0f;
        for (int k = 0; k < in_dim; k++)
            acc = fmaf(__ldg(&xr[k]), ws[k * DIM + lane], acc);
        g_p0[n * DIM + lane] = __float2half(acc);
    }
}

// ---------------- fused GIN layer (fp16 p, 2 edges per warp-load) ------------
// Input:  p_in[n] = h_l[n] @ Wa_l  (half)
// Output: p_out[n] = relu(relu(segsum + self + Ba) @ Wb + Bb) @ Wa_next (half)
// If LAST: accumulate pooled sum of u = relu(...) into g_pool.
template <bool LAST>
__global__ void __launch_bounds__(256)
k_layer(const __half* __restrict__ p_in, __half* __restrict__ p_out,
        const float* __restrict__ Wb, const float* __restrict__ Bbv,
        const float* __restrict__ Bav, const float* __restrict__ Wanext,
        int n_nodes) {
    __shared__ float s_wb[DIM * DIM];
    __shared__ float s_wa[DIM * DIM];
    for (int i = threadIdx.x; i < DIM * DIM; i += blockDim.x) {
        s_wb[i] = Wb[i];
        if (!LAST) s_wa[i] = Wanext[i];
    }
    __syncthreads();

    const __half2* __restrict__ p2 = (const __half2*)p_in;
    int lane = threadIdx.x & 31;
    int half_id = lane >> 4;      // 0 or 1: which edge of the pair
    int fl = lane & 15;           // feature-pair index (features 2fl, 2fl+1)
    float ba_x = Bav[2 * fl], ba_y = Bav[2 * fl + 1];
    float bbv = Bbv[lane];

    int warp = (blockIdx.x * blockDim.x + threadIdx.x) >> 5;
    int nwarp = (gridDim.x * blockDim.x) >> 5;
    float pool = 0.0f;

    for (int n = warp; n < n_nodes; n += nwarp) {
        int beg = g_row[n];
        int end = g_row[n + 1];
        float ax0 = 0.f, ay0 = 0.f, ax1 = 0.f, ay1 = 0.f;
        float ax2 = 0.f, ay2 = 0.f, ax3 = 0.f, ay3 = 0.f;
        float ax4 = 0.f, ay4 = 0.f, ax5 = 0.f, ay5 = 0.f;
        float ax6 = 0.f, ay6 = 0.f, ax7 = 0.f, ay7 = 0.f;
        int e = beg;
        // 16 edges per iteration: 8 independent half2 gathers per lane,
        // each warp-load covers 2 source rows (64B each).
        for (; e + 16 <= end; e += 16) {
            int s0 = g_ssrc[e + 0 + half_id];
            int s1 = g_ssrc[e + 2 + half_id];
            int s2 = g_ssrc[e + 4 + half_id];
            int s3 = g_ssrc[e + 6 + half_id];
            int s4 = g_ssrc[e + 8 + half_id];
            int s5 = g_ssrc[e + 10 + half_id];
            int s6 = g_ssrc[e + 12 + half_id];
            int s7 = g_ssrc[e + 14 + half_id];
            float2 f0 = __half22float2(p2[s0 * 16 + fl]);
            float2 f1 = __half22float2(p2[s1 * 16 + fl]);
            float2 f2 = __half22float2(p2[s2 * 16 + fl]);
            float2 f3 = __half22float2(p2[s3 * 16 + fl]);
            float2 f4 = __half22float2(p2[s4 * 16 + fl]);
            float2 f5 = __half22float2(p2[s5 * 16 + fl]);
            float2 f6 = __half22float2(p2[s6 * 16 + fl]);
            float2 f7 = __half22float2(p2[s7 * 16 + fl]);
            ax0 += f0.x; ay0 += f0.y;
            ax1 += f1.x; ay1 += f1.y;
            ax2 += f2.x; ay2 += f2.y;
            ax3 += f3.x; ay3 += f3.y;
            ax4 += f4.x; ay4 += f4.y;
            ax5 += f5.x; ay5 += f5.y;
            ax6 += f6.x; ay6 += f6.y;
            ax7 += f7.x; ay7 += f7.y;
        }
        // 2-edge remainder
        for (; e + 2 <= end; e += 2) {
            int s = g_ssrc[e + half_id];
            float2 f = __half22float2(p2[s * 16 + fl]);
            ax0 += f.x; ay0 += f.y;
        }
        // single-edge remainder: lower half-warp only
        if (e < end && half_id == 0) {
            int s = g_ssrc[e];
            float2 f = __half22float2(p2[s * 16 + fl]);
            ax0 += f.x; ay0 += f.y;
        }

        float tx = ((ax0 + ax1) + (ax2 + ax3)) + ((ax4 + ax5) + (ax6 + ax7));
        float ty = ((ay0 + ay1) + (ay2 + ay3)) + ((ay4 + ay5) + (ay6 + ay7));
        // combine the two half-warps' partials
        tx += __shfl_xor_sync(0xffffffffu, tx, 16);
        ty += __shfl_xor_sync(0xffffffffu, ty, 16);
        // self term + bias + relu (consistent across both halves)
        float2 sv = __half22float2(p2[n * 16 + fl]);
        tx = fmaxf(tx + sv.x + ba_x, 0.0f);
        ty = fmaxf(ty + sv.y + ba_y, 0.0f);

        // u_j = relu(sum_k t_k * Wb[k][j] + Bb[j]); j = lane
        float u = bbv;
#pragma unroll
        for (int k = 0; k < 16; k++) {
            float tkx = __shfl_sync(0xffffffffu, tx, k);
            float tky = __shfl_sync(0xffffffffu, ty, k);
            u = fmaf(tkx, s_wb[(2 * k) * DIM + lane], u);
            u = fmaf(tky, s_wb[(2 * k + 1) * DIM + lane], u);
        }
        u = fmaxf(u, 0.0f);

        if (!LAST) {
            float o = 0.0f;
#pragma unroll
            for (int k = 0; k < DIM; k++)
                o = fmaf(__shfl_sync(0xffffffffu, u, k), s_wa[k * DIM + lane], o);
            p_out[n * DIM + lane] = __float2half(o);
        } else {
            pool += u;
        }
    }

    if (LAST) {
        __shared__ float sp[8][DIM];
        int w = threadIdx.x >> 5;
        sp[w][lane] = pool;
        __syncthreads();
        if (w == 0) {
            float s = 0.0f;
#pragma unroll
            for (int i = 0; i < 8; i++) s += sp[i][lane];
            atomicAdd(&g_pool[lane], s);
        }
    }
}

// ---------------- head: out = relu(pool @ fc_w + fc_b) @ out_w + out_b -------
__global__ void k_head(const float* __restrict__ fcw, const float* __restrict__ fcb,
                       const float* __restrict__ outw, const float* __restrict__ outb,
                       float* __restrict__ out) {
    __shared__ float g2[DIM];
    int j = threadIdx.x;
    float acc = fcb[j];
    for (int k = 0; k < DIM; k++) acc = fmaf(g_pool[k], fcw[k * DIM + j], acc);
    g2[j] = fmaxf(acc, 0.0f);
    __syncwarp();
    float o = outb[j];
    for (int k = 0; k < DIM; k++) o = fmaf(g2[k], outw[k * DIM + j], o);
    out[j] = o;
}

// ---------------- launch ------------------------------------------------------
extern "C" void kernel_launch(void* const* d_in, const int* in_sizes, int n_in,
                              void* d_out, int out_size) {
    const float* x    = (const float*)d_in[0];
    const int*   ei   = (const int*)d_in[1];
    const float* w1a  = (const float*)d_in[2];
    const float* b1a  = (const float*)d_in[3];
    const float* w1b  = (const float*)d_in[4];
    const float* b1b  = (const float*)d_in[5];
    const float* wa   = (const float*)d_in[6];
    const float* ba   = (const float*)d_in[7];
    const float* wb   = (const float*)d_in[8];
    const float* bb   = (const float*)d_in[9];
    const float* fcw  = (const float*)d_in[10];
    const float* fcb  = (const float*)d_in[11];
    const float* outw = (const float*)d_in[12];
    const float* outb = (const float*)d_in[13];

    int in_dim  = in_sizes[2] / DIM;           // w1a is (in_dim, 32)
    int n_nodes = in_sizes[0] / in_dim;        // x is (n, in_dim)
    int n_edges = in_sizes[1] / 2;             // edge_index is (2, E)
    const int* src = ei;
    const int* dst = ei + n_edges;

    __half *p0, *p1;
    cudaGetSymbolAddress((void**)&p0, g_p0);
    cudaGetSymbolAddress((void**)&p1, g_p1);

    // CSR build + zero pool
    k_zero<<<256, 256>>>(n_nodes);
    k_hist<<<2048, 256>>>(dst, n_edges);
    int nb = (n_nodes + SCAN_BLK - 1) / SCAN_BLK;
    k_scan1<<<nb, SCAN_BLK>>>(n_nodes);
    k_scan2<<<1, NB_MAX>>>(nb);
    k_scan3<<<256, 256>>>(n_nodes, n_edges);
    k_fill<<<2048, 256>>>(src, dst, n_edges);

    // projection to first-layer pre-aggregation space
    k_proj<<<1024, 256>>>(x, w1a, n_nodes, in_dim);

    // 5 fused GIN layers (double-buffered p)
    k_layer<false><<<2048, 256>>>(p0, p1, w1b, b1b, b1a, wa + 0 * DIM * DIM, n_nodes);
    k_layer<false><<<2048, 256>>>(p1, p0, wb + 0 * DIM * DIM, bb + 0 * DIM, ba + 0 * DIM,
                                  wa + 1 * DIM * DIM, n_nodes);
    k_layer<false><<<2048, 256>>>(p0, p1, wb + 1 * DIM * DIM, bb + 1 * DIM, ba + 1 * DIM,
                                  wa + 2 * DIM * DIM, n_nodes);
    k_layer<false><<<2048, 256>>>(p1, p0, wb + 2 * DIM * DIM, bb + 2 * DIM, ba + 2 * DIM,
                                  wa + 3 * DIM * DIM, n_nodes);
    k_layer<true><<<2048, 256>>>(p0, nullptr, wb + 3 * DIM * DIM, bb + 3 * DIM,
                                 ba + 3 * DIM, nullptr, n_nodes);

    // graph head
    k_head<<<1, 32>>>(fcw, fcb, outw, outb, (float*)d_out);
}